// round 2
// baseline (speedup 1.0000x reference)
#include <cuda_runtime.h>

#define H 8192
#define T 64

// 2 MB scratch: pre[t][n] = x[t] . W_ih[n] + b[n]
__device__ float g_pre[T * H];

// ---------------------------------------------------------------------------
// GEMM: pre = x @ W_ih^T + b.   x: (64, 8192) row-major, W: (8192, 8192)
// row-major (both K-contiguous). BM=64 (all t), BN=64, BK=16, 256 threads,
// 4x4 register tile. Grid = 128 blocks.
// ---------------------------------------------------------------------------
__global__ __launch_bounds__(256) void gemm_pre_kernel(
    const float* __restrict__ x,
    const float* __restrict__ W,
    const float* __restrict__ b)
{
    const int BN = 64, BK = 16;
    __shared__ float As[BK][64];   // x^T tile  [k][t]
    __shared__ float Bs[BK][BN];   // W^T tile  [k][n]

    int tid = threadIdx.x;
    int n0  = blockIdx.x * BN;
    int tx  = tid & 15;            // n direction (0..15)
    int ty  = tid >> 4;            // m direction (0..15)

    // global->smem load mapping: 1024 floats per tile, 4 (one float4) each
    int lr = tid >> 2;             // row in tile (t or n), 0..63
    int lk = (tid & 3) * 4;        // k offset, {0,4,8,12}

    float acc[4][4] = {};

    for (int k0 = 0; k0 < H; k0 += BK) {
        float4 av = *(const float4*)(x + (size_t)lr * H + k0 + lk);
        float4 bv = *(const float4*)(W + (size_t)(n0 + lr) * H + k0 + lk);
        __syncthreads();
        As[lk + 0][lr] = av.x; As[lk + 1][lr] = av.y;
        As[lk + 2][lr] = av.z; As[lk + 3][lr] = av.w;
        Bs[lk + 0][lr] = bv.x; Bs[lk + 1][lr] = bv.y;
        Bs[lk + 2][lr] = bv.z; Bs[lk + 3][lr] = bv.w;
        __syncthreads();

        #pragma unroll
        for (int kk = 0; kk < BK; kk++) {
            float a[4], bb[4];
            #pragma unroll
            for (int i = 0; i < 4; i++) a[i]  = As[kk][ty * 4 + i];
            #pragma unroll
            for (int j = 0; j < 4; j++) bb[j] = Bs[kk][tx * 4 + j];
            #pragma unroll
            for (int i = 0; i < 4; i++)
                #pragma unroll
                for (int j = 0; j < 4; j++)
                    acc[i][j] += a[i] * bb[j];
        }
    }

    #pragma unroll
    for (int i = 0; i < 4; i++) {
        int m = ty * 4 + i;
        #pragma unroll
        for (int j = 0; j < 4; j++) {
            int n = n0 + tx * 4 + j;
            g_pre[m * H + n] = acc[i][j] + b[n];
        }
    }
}

// ---------------------------------------------------------------------------
// t = 0: h0 = 0, so out[0][n] = tanh(pre[0][n])
// ---------------------------------------------------------------------------
__global__ void step0_kernel(float* __restrict__ out)
{
    int i = blockIdx.x * blockDim.x + threadIdx.x;
    out[i] = tanhf(g_pre[i]);
}

// ---------------------------------------------------------------------------
// One recurrence step: out_t[n] = tanh(pre_t[n] + W_hh[n,:] . h_prev)
// 512 threads = 16 warps, one row per warp, 512 blocks. h_prev staged in smem
// (32 KB) so the 8192x re-read of h hits the smem crossbar, not L2.
// ---------------------------------------------------------------------------
__global__ __launch_bounds__(512) void gemv_step_kernel(
    const float* __restrict__ W,       // W_hh
    const float* __restrict__ h_prev,  // = out + (t-1)*H
    float* __restrict__ h_out,         // = out + t*H
    int t)
{
    __shared__ float4 sh[H / 4];       // 32 KB

    int tid = threadIdx.x;
    const float4* h4 = (const float4*)h_prev;
    #pragma unroll
    for (int i = 0; i < (H / 4) / 512; i++)   // 4 iters
        sh[tid + i * 512] = h4[tid + i * 512];
    __syncthreads();

    int warp = tid >> 5;
    int lane = tid & 31;
    int row  = blockIdx.x * 16 + warp;

    const float4* w4 = (const float4*)(W + (size_t)row * H);
    float acc = 0.f;
    #pragma unroll 4
    for (int i = lane; i < H / 4; i += 32) {
        float4 w  = w4[i];
        float4 hv = sh[i];
        acc += w.x * hv.x + w.y * hv.y + w.z * hv.z + w.w * hv.w;
    }

    #pragma unroll
    for (int o = 16; o; o >>= 1)
        acc += __shfl_xor_sync(0xffffffffu, acc, o);

    if (lane == 0)
        h_out[row] = tanhf(acc + g_pre[t * H + row]);
}

// ---------------------------------------------------------------------------
extern "C" void kernel_launch(void* const* d_in, const int* in_sizes, int n_in,
                              void* d_out, int out_size)
{
    const float* x    = (const float*)d_in[0];   // (64, 8192)
    const float* W_ih = (const float*)d_in[1];   // (8192, 8192)
    const float* W_hh = (const float*)d_in[2];   // (8192, 8192)
    const float* b    = (const float*)d_in[3];   // (8192,)
    float* out = (float*)d_out;                  // (64*8192,) fp32

    (void)in_sizes; (void)n_in; (void)out_size;

    gemm_pre_kernel<<<H / 64, 256>>>(x, W_ih, b);
    step0_kernel<<<H / 256, 256>>>(out);
    for (int t = 1; t < T; t++) {
        gemv_step_kernel<<<H / 16, 512>>>(W_hh, out + (size_t)(t - 1) * H,
                                          out + (size_t)t * H, t);
    }
}

// round 4
// speedup vs baseline: 1.6255x; 1.6255x over previous
#include <cuda_runtime.h>

#define H 8192
#define T 64

// Scratch (__device__ globals: no allocations allowed in kernel_launch)
__device__ float g_pre[T * H];            // 2 MB:   pre[t][n] = x[t].W_ih[n] + b[n]
__device__ short g_Wq[(size_t)H * H];     // 128 MB: int16-quantized W_hh
__device__ float g_scale[H];              // per-row dequant scale

// ---------------------------------------------------------------------------
// GEMM: pre = x @ W_ih^T + b.  (unchanged from R2 — known good, ~250us)
// ---------------------------------------------------------------------------
__global__ __launch_bounds__(256) void gemm_pre_kernel(
    const float* __restrict__ x,
    const float* __restrict__ W,
    const float* __restrict__ b)
{
    const int BN = 64, BK = 16;
    __shared__ float As[BK][64];
    __shared__ float Bs[BK][BN];

    int tid = threadIdx.x;
    int n0  = blockIdx.x * BN;
    int tx  = tid & 15;
    int ty  = tid >> 4;
    int lr  = tid >> 2;
    int lk  = (tid & 3) * 4;

    float acc[4][4] = {};

    for (int k0 = 0; k0 < H; k0 += BK) {
        float4 av = *(const float4*)(x + (size_t)lr * H + k0 + lk);
        float4 bv = *(const float4*)(W + (size_t)(n0 + lr) * H + k0 + lk);
        __syncthreads();
        As[lk + 0][lr] = av.x; As[lk + 1][lr] = av.y;
        As[lk + 2][lr] = av.z; As[lk + 3][lr] = av.w;
        Bs[lk + 0][lr] = bv.x; Bs[lk + 1][lr] = bv.y;
        Bs[lk + 2][lr] = bv.z; Bs[lk + 3][lr] = bv.w;
        __syncthreads();

        #pragma unroll
        for (int kk = 0; kk < BK; kk++) {
            float a[4], bb[4];
            #pragma unroll
            for (int i = 0; i < 4; i++) a[i]  = As[kk][ty * 4 + i];
            #pragma unroll
            for (int j = 0; j < 4; j++) bb[j] = Bs[kk][tx * 4 + j];
            #pragma unroll
            for (int i = 0; i < 4; i++)
                #pragma unroll
                for (int j = 0; j < 4; j++)
                    acc[i][j] += a[i] * bb[j];
        }
    }

    #pragma unroll
    for (int i = 0; i < 4; i++) {
        int m = ty * 4 + i;
        #pragma unroll
        for (int j = 0; j < 4; j++) {
            int n = n0 + tx * 4 + j;
            g_pre[m * H + n] = acc[i][j] + b[n];
        }
    }
}

// ---------------------------------------------------------------------------
// Quantize W_hh -> int16, one block per row, per-row scale.
// Each thread holds its 32 row elements in registers (1 read of W total).
// ---------------------------------------------------------------------------
__global__ __launch_bounds__(256) void quant_kernel(const float* __restrict__ W)
{
    __shared__ float red[8];
    int row = blockIdx.x;
    int tid = threadIdx.x;
    const float4* w4 = (const float4*)(W + (size_t)row * H);

    float4 v[8];
    float m = 0.f;
    #pragma unroll
    for (int i = 0; i < 8; i++) {
        v[i] = w4[tid + i * 256];
        m = fmaxf(m, fmaxf(fmaxf(fabsf(v[i].x), fabsf(v[i].y)),
                           fmaxf(fabsf(v[i].z), fabsf(v[i].w))));
    }
    #pragma unroll
    for (int o = 16; o; o >>= 1)
        m = fmaxf(m, __shfl_xor_sync(0xffffffffu, m, o));
    if ((tid & 31) == 0) red[tid >> 5] = m;
    __syncthreads();
    float rowmax = fmaxf(fmaxf(fmaxf(red[0], red[1]), fmaxf(red[2], red[3])),
                         fmaxf(fmaxf(red[4], red[5]), fmaxf(red[6], red[7])));
    rowmax = fmaxf(rowmax, 1e-30f);           // guard all-zero row
    float inv = 32767.0f / rowmax;

    short4* q4 = (short4*)(g_Wq + (size_t)row * H);
    #pragma unroll
    for (int i = 0; i < 8; i++) {
        short4 q;
        q.x = (short)__float2int_rn(v[i].x * inv);
        q.y = (short)__float2int_rn(v[i].y * inv);
        q.z = (short)__float2int_rn(v[i].z * inv);
        q.w = (short)__float2int_rn(v[i].w * inv);
        q4[tid + i * 256] = q;
    }
    if (tid == 0) g_scale[row] = rowmax / 32767.0f;
}

// ---------------------------------------------------------------------------
// t = 0: h0 = 0 -> out[0][n] = tanh(pre[0][n])
// ---------------------------------------------------------------------------
__global__ void step0_kernel(float* __restrict__ out)
{
    int i = blockIdx.x * blockDim.x + threadIdx.x;
    out[i] = tanhf(g_pre[i]);
}

// ---------------------------------------------------------------------------
// Recurrence step on int16 weights: out_t[n] = tanh(s[n]*(q[n,:].h) + pre_t[n])
// 16 warps/block, one row per warp, h_prev staged in smem (fp32, 32 KB).
// Per-lane: 32 x LDG.128 (8 shorts each), contiguous 512B/warp/iter.
// ---------------------------------------------------------------------------
__global__ __launch_bounds__(512) void gemv_q_kernel(
    const float* __restrict__ h_prev,
    float* __restrict__ h_out,
    int t)
{
    __shared__ float4 sh[H / 4];   // 32 KB

    int tid = threadIdx.x;
    const float4* h4 = (const float4*)h_prev;
    #pragma unroll
    for (int i = 0; i < (H / 4) / 512; i++)
        sh[tid + i * 512] = h4[tid + i * 512];
    __syncthreads();

    int warp = tid >> 5;
    int lane = tid & 31;
    int row  = blockIdx.x * 16 + warp;

    const int4* q4 = (const int4*)(g_Wq + (size_t)row * H);
    float acc0 = 0.f, acc1 = 0.f;
    #pragma unroll 4
    for (int i = lane; i < H / 8; i += 32) {     // 1024 int4 per row, 32 iters
        int4   q  = q4[i];
        float4 ha = sh[2 * i];
        float4 hb = sh[2 * i + 1];
        acc0 += (float)(short)(q.x & 0xffff) * ha.x;
        acc1 += (float)(short)(q.x >> 16)    * ha.y;
        acc0 += (float)(short)(q.y & 0xffff) * ha.z;
        acc1 += (float)(short)(q.y >> 16)    * ha.w;
        acc0 += (float)(short)(q.z & 0xffff) * hb.x;
        acc1 += (float)(short)(q.z >> 16)    * hb.y;
        acc0 += (float)(short)(q.w & 0xffff) * hb.z;
        acc1 += (float)(short)(q.w >> 16)    * hb.w;
    }
    float acc = acc0 + acc1;

    #pragma unroll
    for (int o = 16; o; o >>= 1)
        acc += __shfl_xor_sync(0xffffffffu, acc, o);

    if (lane == 0)
        h_out[row] = tanhf(acc * g_scale[row] + g_pre[t * H + row]);
}

// ---------------------------------------------------------------------------
extern "C" void kernel_launch(void* const* d_in, const int* in_sizes, int n_in,
                              void* d_out, int out_size)
{
    const float* x    = (const float*)d_in[0];   // (64, 8192)
    const float* W_ih = (const float*)d_in[1];   // (8192, 8192)
    const float* W_hh = (const float*)d_in[2];   // (8192, 8192)
    const float* b    = (const float*)d_in[3];   // (8192,)
    float* out = (float*)d_out;                  // (64*8192,) fp32

    (void)in_sizes; (void)n_in; (void)out_size;

    quant_kernel<<<H, 256>>>(W_hh);              // ~75us, overlappable later
    gemm_pre_kernel<<<H / 64, 256>>>(x, W_ih, b);
    step0_kernel<<<H / 256, 256>>>(out);
    for (int t = 1; t < T; t++) {
        gemv_q_kernel<<<H / 16, 512>>>(out + (size_t)(t - 1) * H,
                                       out + (size_t)t * H, t);
    }
}

// round 5
// speedup vs baseline: 1.7180x; 1.0569x over previous
#include <cuda_runtime.h>

#define H 8192
#define T 64
#define KSPLIT 4

// ---- __device__ scratch (no allocations allowed) ----
__device__ float g_pre[T * H];                       // 2 MB
__device__ float g_part[KSPLIT * T * H];             // 8 MB split-K partials
__device__ signed char g_Whi[(size_t)H * H];         // 64 MB: high 8 bits of q12
__device__ unsigned char g_Wlo[(size_t)H * H / 2];   // 32 MB: low 4 bits of q12
__device__ float g_scale[H];                         // per-row dequant scale

// ---------------------------------------------------------------------------
// f32x2 helpers (packed dual-fp32 FMA, Blackwell; PTX-only per SASS quickref)
// ---------------------------------------------------------------------------
__device__ __forceinline__ void ffma2(unsigned long long& d,
                                      unsigned long long a,
                                      unsigned long long b)
{
    asm("fma.rn.f32x2 %0, %1, %2, %3;" : "=l"(d) : "l"(a), "l"(b), "l"(d));
}
__device__ __forceinline__ unsigned long long dup2(float a)
{
    unsigned long long r;
    asm("mov.b64 %0, {%1, %1};" : "=l"(r) : "r"(__float_as_int(a)));
    return r;
}
__device__ __forceinline__ float2 unpack2(unsigned long long v)
{
    float2 f;
    f.x = __int_as_float((int)(v & 0xffffffffu));
    f.y = __int_as_float((int)(v >> 32));
    return f;
}

// ---------------------------------------------------------------------------
// GEMM split-K: g_part[ks] = x @ W_ih^T over K-chunk ks.
// BM=64 (all t), BN=128, BK=16, 128 threads, 8x8 per-thread tile (2x2 blocks
// of 4x4), inner product via fma.rn.f32x2. Grid = (64, KSPLIT).
// ---------------------------------------------------------------------------
__global__ __launch_bounds__(128) void gemm_pre_kernel(
    const float* __restrict__ x,
    const float* __restrict__ W)
{
    __shared__ float As[16][64];    // [k][m]
    __shared__ float Bs[16][128];   // [k][n]

    int tid = threadIdx.x;
    int n0  = blockIdx.x * 128;
    int ks  = blockIdx.y;
    int kb  = ks * (H / KSPLIT);
    int ke  = kb + (H / KSPLIT);

    int tx = tid & 15;              // n (0..15)
    int ty = tid >> 4;              // m (0..7)

    unsigned long long acc[8][4];
    #pragma unroll
    for (int i = 0; i < 8; i++)
        #pragma unroll
        for (int j = 0; j < 4; j++) acc[i][j] = 0ull;

    for (int k0 = kb; k0 < ke; k0 += 16) {
        // global -> smem (transposed)
        float4 av[2], bv[4];
        #pragma unroll
        for (int i = 0; i < 2; i++) {
            int i2 = tid + i * 128;                 // 0..255
            int m = i2 >> 2, kq = (i2 & 3) * 4;
            av[i] = *(const float4*)(x + (size_t)m * H + k0 + kq);
        }
        #pragma unroll
        for (int i = 0; i < 4; i++) {
            int i2 = tid + i * 128;                 // 0..511
            int n = i2 >> 2, kq = (i2 & 3) * 4;
            bv[i] = *(const float4*)(W + (size_t)(n0 + n) * H + k0 + kq);
        }
        __syncthreads();
        #pragma unroll
        for (int i = 0; i < 2; i++) {
            int i2 = tid + i * 128;
            int m = i2 >> 2, kq = (i2 & 3) * 4;
            As[kq + 0][m] = av[i].x; As[kq + 1][m] = av[i].y;
            As[kq + 2][m] = av[i].z; As[kq + 3][m] = av[i].w;
        }
        #pragma unroll
        for (int i = 0; i < 4; i++) {
            int i2 = tid + i * 128;
            int n = i2 >> 2, kq = (i2 & 3) * 4;
            Bs[kq + 0][n] = bv[i].x; Bs[kq + 1][n] = bv[i].y;
            Bs[kq + 2][n] = bv[i].z; Bs[kq + 3][n] = bv[i].w;
        }
        __syncthreads();

        #pragma unroll
        for (int kk = 0; kk < 16; kk++) {
            float4 a0 = *(const float4*)&As[kk][ty * 4];
            float4 a1 = *(const float4*)&As[kk][32 + ty * 4];
            ulonglong2 bb0 = *(const ulonglong2*)&Bs[kk][tx * 4];
            ulonglong2 bb1 = *(const ulonglong2*)&Bs[kk][64 + tx * 4];
            unsigned long long am[8] = {
                dup2(a0.x), dup2(a0.y), dup2(a0.z), dup2(a0.w),
                dup2(a1.x), dup2(a1.y), dup2(a1.z), dup2(a1.w) };
            #pragma unroll
            for (int m = 0; m < 8; m++) {
                ffma2(acc[m][0], am[m], bb0.x);
                ffma2(acc[m][1], am[m], bb0.y);
                ffma2(acc[m][2], am[m], bb1.x);
                ffma2(acc[m][3], am[m], bb1.y);
            }
        }
        __syncthreads();
    }

    float* outp = g_part + (size_t)ks * T * H;
    #pragma unroll
    for (int m = 0; m < 8; m++) {
        int row = (m < 4) ? (ty * 4 + m) : (32 + ty * 4 + (m - 4));
        #pragma unroll
        for (int p = 0; p < 4; p++) {
            int nb = (p < 2) ? (tx * 4 + 2 * p) : (64 + tx * 4 + 2 * (p - 2));
            *(float2*)&outp[(size_t)row * H + n0 + nb] = unpack2(acc[m][p]);
        }
    }
}

// g_pre[i] = b[i % H] + sum_ks g_part[ks][i]
__global__ void reduce_pre_kernel(const float* __restrict__ b)
{
    int i = blockIdx.x * blockDim.x + threadIdx.x;   // 0 .. T*H-1
    float s = b[i & (H - 1)];
    #pragma unroll
    for (int ks = 0; ks < KSPLIT; ks++) s += g_part[ks * T * H + i];
    g_pre[i] = s;
}

// ---------------------------------------------------------------------------
// Quantize W_hh -> 12-bit (hi 8 bits + lo 4 bits), per-row scale.
// ---------------------------------------------------------------------------
__global__ __launch_bounds__(256) void quant_kernel(const float* __restrict__ W)
{
    __shared__ float red[8];
    int row = blockIdx.x;
    int tid = threadIdx.x;
    const float4* w4 = (const float4*)(W + (size_t)row * H);

    float4 v[8];
    float m = 0.f;
    #pragma unroll
    for (int i = 0; i < 8; i++) {
        v[i] = w4[tid + i * 256];
        m = fmaxf(m, fmaxf(fmaxf(fabsf(v[i].x), fabsf(v[i].y)),
                           fmaxf(fabsf(v[i].z), fabsf(v[i].w))));
    }
    #pragma unroll
    for (int o = 16; o; o >>= 1)
        m = fmaxf(m, __shfl_xor_sync(0xffffffffu, m, o));
    if ((tid & 31) == 0) red[tid >> 5] = m;
    __syncthreads();
    float rowmax = fmaxf(fmaxf(fmaxf(red[0], red[1]), fmaxf(red[2], red[3])),
                         fmaxf(fmaxf(red[4], red[5]), fmaxf(red[6], red[7])));
    rowmax = fmaxf(rowmax, 1e-30f);
    float inv = 2047.0f / rowmax;

    char4*          hi4 = (char4*)(g_Whi + (size_t)row * H);            // per float4
    unsigned short* lo2 = (unsigned short*)(g_Wlo + (size_t)row * (H / 2));

    #pragma unroll
    for (int i = 0; i < 8; i++) {
        int j = tid + i * 256;                       // float4 index in row
        int q0 = max(-2047, min(2047, __float2int_rn(v[i].x * inv)));
        int q1 = max(-2047, min(2047, __float2int_rn(v[i].y * inv)));
        int q2 = max(-2047, min(2047, __float2int_rn(v[i].z * inv)));
        int q3 = max(-2047, min(2047, __float2int_rn(v[i].w * inv)));
        char4 hc;
        hc.x = (signed char)(q0 >> 4);
        hc.y = (signed char)(q1 >> 4);
        hc.z = (signed char)(q2 >> 4);
        hc.w = (signed char)(q3 >> 4);
        hi4[j] = hc;
        lo2[j] = (unsigned short)((q0 & 15) | ((q1 & 15) << 4) |
                                  ((q2 & 15) << 8) | ((q3 & 15) << 12));
    }
    if (tid == 0) g_scale[row] = rowmax / 2047.0f;
}

// ---------------------------------------------------------------------------
// t = 0: h0 = 0 -> out[0][n] = tanh(pre[0][n])
// ---------------------------------------------------------------------------
__global__ void step0_kernel(float* __restrict__ out)
{
    int i = blockIdx.x * blockDim.x + threadIdx.x;
    out[i] = tanhf(g_pre[i]);
}

// ---------------------------------------------------------------------------
// Recurrence step on 12-bit weights (L2-resident, 96 MB total).
// 16 warps/block, one row per warp. h in even/odd smem arrays (conflict-free
// LDS.128). Per lane per iter: 8 weights = uint2 hi + uint lo.
// ---------------------------------------------------------------------------
__global__ __launch_bounds__(512) void gemv_q_kernel(
    const float* __restrict__ h_prev,
    float* __restrict__ h_out,
    int t)
{
    __shared__ float4 shA[H / 8];   // even float4s of h, 16 KB
    __shared__ float4 shB[H / 8];   // odd  float4s of h, 16 KB

    int tid = threadIdx.x;
    const float4* h4 = (const float4*)h_prev;
    #pragma unroll
    for (int i = 0; i < (H / 4) / 512; i++) {       // 4 iters
        int j = tid + i * 512;
        float4 v = h4[j];
        if (j & 1) shB[j >> 1] = v; else shA[j >> 1] = v;
    }
    __syncthreads();

    int warp = tid >> 5;
    int lane = tid & 31;
    int row  = blockIdx.x * 16 + warp;

    const uint2*    hi2 = (const uint2*)(g_Whi + (size_t)row * H);
    const unsigned* lo4 = (const unsigned*)(g_Wlo + (size_t)row * (H / 2));

    float acc0 = 0.f, acc1 = 0.f;
    #pragma unroll 4
    for (int i = lane; i < H / 8; i += 32) {        // 32 iters
        uint2    hw = hi2[i];
        unsigned lw = lo4[i];
        float4   ha = shA[i];
        float4   hb = shB[i];

        int q0 = ((int)(signed char)(hw.x      )) * 16 + (int)( lw        & 15);
        int q1 = ((int)(signed char)(hw.x >>  8)) * 16 + (int)((lw >>  4) & 15);
        int q2 = ((int)(signed char)(hw.x >> 16)) * 16 + (int)((lw >>  8) & 15);
        int q3 = ((int)(signed char)(hw.x >> 24)) * 16 + (int)((lw >> 12) & 15);
        int q4 = ((int)(signed char)(hw.y      )) * 16 + (int)((lw >> 16) & 15);
        int q5 = ((int)(signed char)(hw.y >>  8)) * 16 + (int)((lw >> 20) & 15);
        int q6 = ((int)(signed char)(hw.y >> 16)) * 16 + (int)((lw >> 24) & 15);
        int q7 = ((int)(signed char)(hw.y >> 24)) * 16 + (int)((lw >> 28) & 15);

        acc0 += (float)q0 * ha.x;  acc1 += (float)q1 * ha.y;
        acc0 += (float)q2 * ha.z;  acc1 += (float)q3 * ha.w;
        acc0 += (float)q4 * hb.x;  acc1 += (float)q5 * hb.y;
        acc0 += (float)q6 * hb.z;  acc1 += (float)q7 * hb.w;
    }
    float acc = acc0 + acc1;

    #pragma unroll
    for (int o = 16; o; o >>= 1)
        acc += __shfl_xor_sync(0xffffffffu, acc, o);

    if (lane == 0)
        h_out[row] = tanhf(acc * g_scale[row] + g_pre[t * H + row]);
}

// ---------------------------------------------------------------------------
extern "C" void kernel_launch(void* const* d_in, const int* in_sizes, int n_in,
                              void* d_out, int out_size)
{
    const float* x    = (const float*)d_in[0];   // (64, 8192)
    const float* W_ih = (const float*)d_in[1];   // (8192, 8192)
    const float* W_hh = (const float*)d_in[2];   // (8192, 8192)
    const float* b    = (const float*)d_in[3];   // (8192,)
    float* out = (float*)d_out;                  // (64*8192,) fp32

    (void)in_sizes; (void)n_in; (void)out_size;

    gemm_pre_kernel<<<dim3(H / 128, KSPLIT), 128>>>(x, W_ih);
    reduce_pre_kernel<<<(T * H) / 256, 256>>>(b);
    quant_kernel<<<H, 256>>>(W_hh);              // last before steps: L2-warm
    step0_kernel<<<H / 256, 256>>>(out);
    for (int t = 1; t < T; t++) {
        gemv_q_kernel<<<H / 16, 512>>>(out + (size_t)(t - 1) * H,
                                       out + (size_t)t * H, t);
    }
}

// round 7
// speedup vs baseline: 2.7549x; 1.6035x over previous
#include <cuda_runtime.h>

#define H 8192
#define T 64

// ---- __device__ scratch (no allocations allowed) ----
__device__ float g_pre[T * H];                              // 2 MB
__device__ signed char g_Whi[(size_t)H * H];                // 64 MB hi bytes (q>>4)
__device__ unsigned char g_Wlo[(size_t)H * H / 2];          // 32 MB lo nibbles
__device__ float g_scale[H];                                // rowmax/(2047*32767)
__device__ __align__(16) short g_hq[2][H];                  // int16 h double buffer

// ---------------------------------------------------------------------------
// f32x2 helpers
// ---------------------------------------------------------------------------
__device__ __forceinline__ void ffma2(unsigned long long& d,
                                      unsigned long long a,
                                      unsigned long long b)
{
    asm("fma.rn.f32x2 %0, %1, %2, %3;" : "=l"(d) : "l"(a), "l"(b), "l"(d));
}
__device__ __forceinline__ unsigned long long dup2(float a)
{
    unsigned long long r;
    asm("mov.b64 %0, {%1, %1};" : "=l"(r) : "r"(__float_as_int(a)));
    return r;
}
__device__ __forceinline__ float2 unpack2(unsigned long long v)
{
    float2 f;
    f.x = __int_as_float((int)(v & 0xffffffffu));
    f.y = __int_as_float((int)(v >> 32));
    return f;
}

// ---------------------------------------------------------------------------
// GEMM: pre = x @ W_ih^T + b.  R2 structure (known-good), f32x2 inner product.
// BM=64, BN=64, BK=16, 256 threads, 4x4 per-thread tile. Grid = 128 blocks.
// ---------------------------------------------------------------------------
__global__ __launch_bounds__(256) void gemm_pre_kernel(
    const float* __restrict__ x,
    const float* __restrict__ W,
    const float* __restrict__ b)
{
    const int BN = 64, BK = 16;
    __shared__ float As[BK][64];
    __shared__ float Bs[BK][BN];

    int tid = threadIdx.x;
    int n0  = blockIdx.x * BN;
    int tx  = tid & 15;
    int ty  = tid >> 4;
    int lr  = tid >> 2;
    int lk  = (tid & 3) * 4;

    unsigned long long acc[4][2];
    #pragma unroll
    for (int i = 0; i < 4; i++) { acc[i][0] = 0ull; acc[i][1] = 0ull; }

    for (int k0 = 0; k0 < H; k0 += BK) {
        float4 av = *(const float4*)(x + (size_t)lr * H + k0 + lk);
        float4 bv = *(const float4*)(W + (size_t)(n0 + lr) * H + k0 + lk);
        __syncthreads();
        As[lk + 0][lr] = av.x; As[lk + 1][lr] = av.y;
        As[lk + 2][lr] = av.z; As[lk + 3][lr] = av.w;
        Bs[lk + 0][lr] = bv.x; Bs[lk + 1][lr] = bv.y;
        Bs[lk + 2][lr] = bv.z; Bs[lk + 3][lr] = bv.w;
        __syncthreads();

        #pragma unroll
        for (int kk = 0; kk < BK; kk++) {
            float4 af = *(const float4*)&As[kk][ty * 4];
            ulonglong2 bb = *(const ulonglong2*)&Bs[kk][tx * 4];
            unsigned long long am[4] = { dup2(af.x), dup2(af.y),
                                         dup2(af.z), dup2(af.w) };
            #pragma unroll
            for (int i = 0; i < 4; i++) {
                ffma2(acc[i][0], am[i], bb.x);
                ffma2(acc[i][1], am[i], bb.y);
            }
        }
    }

    #pragma unroll
    for (int i = 0; i < 4; i++) {
        int m = ty * 4 + i;
        #pragma unroll
        for (int j = 0; j < 2; j++) {
            int n = n0 + tx * 4 + 2 * j;
            float2 p = unpack2(acc[i][j]);
            p.x += b[n];
            p.y += b[n + 1];
            *(float2*)&g_pre[(size_t)m * H + n] = p;
        }
    }
}

// ---------------------------------------------------------------------------
// Quantize W_hh -> 12-bit, packed for dp2a consumption:
//   per 8-weight group g: hi2[g] = uint2 of hi bytes (q>>4) in natural order,
//   lo4[g] = nibbles interleaved (n0,n4,n1,n5,n2,n6,n3,n7) so that
//   lw & 0x0F0F0F0F = bytes(n0,n1,n2,n3), (lw>>4)&0x0F0F0F0F = (n4..n7).
// ---------------------------------------------------------------------------
__global__ __launch_bounds__(256) void quant_kernel(const float* __restrict__ W)
{
    __shared__ float red[8];
    int row = blockIdx.x;
    int tid = threadIdx.x;
    const float4* w4 = (const float4*)(W + (size_t)row * H);

    float4 va[4], vb[4];
    float m = 0.f;
    #pragma unroll
    for (int k = 0; k < 4; k++) {
        int g = tid + k * 256;          // group index 0..1023
        va[k] = w4[2 * g];
        vb[k] = w4[2 * g + 1];
        m = fmaxf(m, fmaxf(fmaxf(fabsf(va[k].x), fabsf(va[k].y)),
                           fmaxf(fabsf(va[k].z), fabsf(va[k].w))));
        m = fmaxf(m, fmaxf(fmaxf(fabsf(vb[k].x), fabsf(vb[k].y)),
                           fmaxf(fabsf(vb[k].z), fabsf(vb[k].w))));
    }
    #pragma unroll
    for (int o = 16; o; o >>= 1)
        m = fmaxf(m, __shfl_xor_sync(0xffffffffu, m, o));
    if ((tid & 31) == 0) red[tid >> 5] = m;
    __syncthreads();
    float rowmax = fmaxf(fmaxf(fmaxf(red[0], red[1]), fmaxf(red[2], red[3])),
                         fmaxf(fmaxf(red[4], red[5]), fmaxf(red[6], red[7])));
    rowmax = fmaxf(rowmax, 1e-30f);
    float inv = 2047.0f / rowmax;

    uint2*    hi2 = (uint2*)(g_Whi + (size_t)row * H);
    unsigned* lo4 = (unsigned*)(g_Wlo + (size_t)row * (H / 2));

    #pragma unroll
    for (int k = 0; k < 4; k++) {
        int g = tid + k * 256;
        int q[8];
        q[0] = max(-2047, min(2047, __float2int_rn(va[k].x * inv)));
        q[1] = max(-2047, min(2047, __float2int_rn(va[k].y * inv)));
        q[2] = max(-2047, min(2047, __float2int_rn(va[k].z * inv)));
        q[3] = max(-2047, min(2047, __float2int_rn(va[k].w * inv)));
        q[4] = max(-2047, min(2047, __float2int_rn(vb[k].x * inv)));
        q[5] = max(-2047, min(2047, __float2int_rn(vb[k].y * inv)));
        q[6] = max(-2047, min(2047, __float2int_rn(vb[k].z * inv)));
        q[7] = max(-2047, min(2047, __float2int_rn(vb[k].w * inv)));

        unsigned w0 = ((unsigned)((q[0] >> 4) & 0xFF))
                    | ((unsigned)((q[1] >> 4) & 0xFF) << 8)
                    | ((unsigned)((q[2] >> 4) & 0xFF) << 16)
                    | ((unsigned)((q[3] >> 4) & 0xFF) << 24);
        unsigned w1 = ((unsigned)((q[4] >> 4) & 0xFF))
                    | ((unsigned)((q[5] >> 4) & 0xFF) << 8)
                    | ((unsigned)((q[6] >> 4) & 0xFF) << 16)
                    | ((unsigned)((q[7] >> 4) & 0xFF) << 24);
        unsigned lw = (unsigned)(q[0] & 15)
                    | ((unsigned)(q[4] & 15) << 4)
                    | ((unsigned)(q[1] & 15) << 8)
                    | ((unsigned)(q[5] & 15) << 12)
                    | ((unsigned)(q[2] & 15) << 16)
                    | ((unsigned)(q[6] & 15) << 20)
                    | ((unsigned)(q[3] & 15) << 24)
                    | ((unsigned)(q[7] & 15) << 28);
        hi2[g] = make_uint2(w0, w1);
        lo4[g] = lw;
    }
    if (tid == 0) g_scale[row] = rowmax / (2047.0f * 32767.0f);
}

// ---------------------------------------------------------------------------
// t = 0: h0 = 0 -> out[0][n] = tanh(pre[0][n]); also int16-quantize h.
// ---------------------------------------------------------------------------
__global__ void step0_kernel(float* __restrict__ out)
{
    int i = blockIdx.x * blockDim.x + threadIdx.x;
    float h = tanhf(g_pre[i]);
    out[i] = h;
    g_hq[0][i] = (short)__float2int_rn(h * 32767.0f);
}

// ---------------------------------------------------------------------------
// Recurrence step, dp2a on 12-bit weights + int16 h (smem).
// 16 warps/block, one row per warp, 512 blocks.
//   dot = scale_row/(32767) * (16*sum(hi_i*hq_i) + sum(lo_i*hq_i))  (folded)
// Weights loaded with L2::evict_last policy to pin the 96 MB set in L2.
// ---------------------------------------------------------------------------
__global__ __launch_bounds__(512) void gemv_q_kernel(
    float* __restrict__ h_out,   // = out + t*H
    int t)
{
    __shared__ unsigned sh[H / 2];   // 4096 u32 = 16 KB, (h[2j],h[2j+1]) int16x2

    int tid = threadIdx.x;
    const uint4* hq4 = (const uint4*)g_hq[(t - 1) & 1];
    uint4* sh4 = (uint4*)sh;
    #pragma unroll
    for (int i = 0; i < 2; i++)
        sh4[tid + i * 512] = hq4[tid + i * 512];
    __syncthreads();

    int warp = tid >> 5;
    int lane = tid & 31;
    int row  = blockIdx.x * 16 + warp;

    unsigned long long pol;
    asm("createpolicy.fractional.L2::evict_last.b64 %0, 1.0;" : "=l"(pol));

    const uint2*    hi2 = (const uint2*)(g_Whi + (size_t)row * H);
    const unsigned* lo4 = (const unsigned*)(g_Wlo + (size_t)row * (H / 2));

    int accH = 0, accL = 0;
    #pragma unroll 4
    for (int i = lane; i < H / 8; i += 32) {        // 32 iters, 8 weights each
        unsigned hw0, hw1, lw;
        asm("ld.global.nc.L2::cache_hint.v2.u32 {%0,%1}, [%2], %3;"
            : "=r"(hw0), "=r"(hw1) : "l"(hi2 + i), "l"(pol));
        asm("ld.global.nc.L2::cache_hint.u32 %0, [%1], %2;"
            : "=r"(lw) : "l"(lo4 + i), "l"(pol));
        uint4 hv = *(const uint4*)&sh[4 * i];
        unsigned b0 = lw & 0x0F0F0F0Fu;
        unsigned b1 = (lw >> 4) & 0x0F0F0F0Fu;
        asm("dp2a.lo.s32.s32 %0, %1, %2, %0;" : "+r"(accH) : "r"(hv.x), "r"(hw0));
        asm("dp2a.hi.s32.s32 %0, %1, %2, %0;" : "+r"(accH) : "r"(hv.y), "r"(hw0));
        asm("dp2a.lo.s32.s32 %0, %1, %2, %0;" : "+r"(accH) : "r"(hv.z), "r"(hw1));
        asm("dp2a.hi.s32.s32 %0, %1, %2, %0;" : "+r"(accH) : "r"(hv.w), "r"(hw1));
        asm("dp2a.lo.s32.u32 %0, %1, %2, %0;" : "+r"(accL) : "r"(hv.x), "r"(b0));
        asm("dp2a.hi.s32.u32 %0, %1, %2, %0;" : "+r"(accL) : "r"(hv.y), "r"(b0));
        asm("dp2a.lo.s32.u32 %0, %1, %2, %0;" : "+r"(accL) : "r"(hv.z), "r"(b1));
        asm("dp2a.hi.s32.u32 %0, %1, %2, %0;" : "+r"(accL) : "r"(hv.w), "r"(b1));
    }

    float acc = fmaf(16.0f, (float)accH, (float)accL);
    #pragma unroll
    for (int o = 16; o; o >>= 1)
        acc += __shfl_xor_sync(0xffffffffu, acc, o);

    if (lane == 0) {
        float h = tanhf(acc * g_scale[row] + g_pre[t * H + row]);
        h_out[row] = h;
        g_hq[t & 1][row] = (short)__float2int_rn(h * 32767.0f);
    }
}

// ---------------------------------------------------------------------------
extern "C" void kernel_launch(void* const* d_in, const int* in_sizes, int n_in,
                              void* d_out, int out_size)
{
    const float* x    = (const float*)d_in[0];   // (64, 8192)
    const float* W_ih = (const float*)d_in[1];   // (8192, 8192)
    const float* W_hh = (const float*)d_in[2];   // (8192, 8192)
    const float* b    = (const float*)d_in[3];   // (8192,)
    float* out = (float*)d_out;                  // (64*8192,) fp32

    (void)in_sizes; (void)n_in; (void)out_size;

    gemm_pre_kernel<<<H / 64, 256>>>(x, W_ih, b);
    quant_kernel<<<H, 256>>>(W_hh);              // last before steps: L2-warm
    step0_kernel<<<H / 256, 256>>>(out);
    for (int t = 1; t < T; t++) {
        gemv_q_kernel<<<H / 16, 512>>>(out + (size_t)t * H, t);
    }
}